// round 12
// baseline (speedup 1.0000x reference)
#include <cuda_runtime.h>
#include <cuda_bf16.h>
#include <cstdint>

// NonlocalBlock: B=4, C=256, Ci=128, H=W=64 (N=4096)
// out = BN(w_out @ softmax(theta^T phi) @ g^T) + x
// HMMA bf16 + bf16x2 hi/lo compensation (3 chains).
// R12: attn uses 512 threads (16 warps, 4/SMSP) with m-half QK / c-half PV
// split and P exchanged through smem, XOR-swizzled tiles (no padding).

namespace {
constexpr int B  = 4;
constexpr int C  = 256;
constexpr int CI = 128;
constexpr int N  = 4096;
}

// ---- scratch (static device globals; no runtime allocation allowed) ----
__device__ float d_y[B * CI * N];
__device__ float d_wy[B * C * N];
__device__ float d_psum[C * 128];
__device__ float d_psq[C * 128];
__device__ float d_bnA[C];
__device__ float d_bnB[C];
__device__ alignas(16) __nv_bfloat16 d_thT_hi[B * N * CI];  // [b][n][ci]
__device__ alignas(16) __nv_bfloat16 d_thT_lo[B * N * CI];
__device__ alignas(16) __nv_bfloat16 d_phT_hi[B * N * CI];  // [b][m][ci]
__device__ alignas(16) __nv_bfloat16 d_phT_lo[B * N * CI];
__device__ alignas(16) __nv_bfloat16 d_g_hi[B * CI * N];    // [b][c][m]
__device__ alignas(16) __nv_bfloat16 d_g_lo[B * CI * N];
__device__ alignas(16) __nv_bfloat16 d_W_hi[384 * 256];
__device__ alignas(16) __nv_bfloat16 d_W_lo[384 * 256];
__device__ alignas(16) __nv_bfloat16 d_x_hi[B * C * N];     // [b][c][n]
__device__ alignas(16) __nv_bfloat16 d_x_lo[B * C * N];

// ============================================================================
// helpers
// ============================================================================
__device__ __forceinline__ uint32_t smem_u32(const void* p) {
    uint32_t a;
    asm("{ .reg .u64 t; cvta.to.shared.u64 t, %1; cvt.u32.u64 %0, t; }" : "=r"(a) : "l"(p));
    return a;
}
__device__ __forceinline__ uint16_t f2bf(float v) {
    return __bfloat16_as_ushort(__float2bfloat16(v));
}
__device__ __forceinline__ float bf2f(uint16_t u) {
    return __bfloat162float(__ushort_as_bfloat16(u));
}
__device__ __forceinline__ uint32_t pack2(uint16_t lo, uint16_t hi) {
    return (uint32_t)lo | ((uint32_t)hi << 16);
}
__device__ __forceinline__ void mma_bf16(float* c,
                                         uint32_t a0, uint32_t a1, uint32_t a2, uint32_t a3,
                                         uint32_t b0, uint32_t b1) {
    asm volatile(
        "mma.sync.aligned.m16n8k16.row.col.f32.bf16.bf16.f32 "
        "{%0,%1,%2,%3}, {%4,%5,%6,%7}, {%8,%9}, {%0,%1,%2,%3};"
        : "+f"(c[0]), "+f"(c[1]), "+f"(c[2]), "+f"(c[3])
        : "r"(a0), "r"(a1), "r"(a2), "r"(a3), "r"(b0), "r"(b1));
}
__device__ __forceinline__ void ldsm_x4(uint32_t addr, uint32_t& r0, uint32_t& r1,
                                        uint32_t& r2, uint32_t& r3) {
    asm volatile("ldmatrix.sync.aligned.m8n8.x4.shared.b16 {%0,%1,%2,%3}, [%4];"
                 : "=r"(r0), "=r"(r1), "=r"(r2), "=r"(r3) : "r"(addr));
}
__device__ __forceinline__ void ldsm_x4_t(uint32_t addr, uint32_t& r0, uint32_t& r1,
                                          uint32_t& r2, uint32_t& r3) {
    asm volatile("ldmatrix.sync.aligned.m8n8.x4.trans.shared.b16 {%0,%1,%2,%3}, [%4];"
                 : "=r"(r0), "=r"(r1), "=r"(r2), "=r"(r3) : "r"(addr));
}
__device__ __forceinline__ void cp16(uint32_t saddr, const void* gaddr) {
    asm volatile("cp.async.cg.shared.global [%0], [%1], 16;" :: "r"(saddr), "l"(gaddr));
}
__device__ __forceinline__ void sts32(uint32_t addr, uint32_t v) {
    asm volatile("st.shared.u32 [%0], %1;" :: "r"(addr), "r"(v) : "memory");
}
#define CP_COMMIT() asm volatile("cp.async.commit_group;" ::: "memory")
#define CP_WAIT(n)  asm volatile("cp.async.wait_group %0;" :: "n"(n) : "memory")

// ============================================================================
// K0a: split weights. grid 384 x 256.
// ============================================================================
__global__ void splitw_kernel(const float* __restrict__ w_g,
                              const float* __restrict__ w_t,
                              const float* __restrict__ w_p)
{
    int row = blockIdx.x, t = threadIdx.x;
    const float* src = (row < 128) ? w_g + (size_t)row * 256
                     : (row < 256) ? w_t + (size_t)(row - 128) * 256
                                   : w_p + (size_t)(row - 256) * 256;
    float v = src[t];
    uint16_t h = f2bf(v);
    d_W_hi[(size_t)row * 256 + t] = __ushort_as_bfloat16(h);
    d_W_lo[(size_t)row * 256 + t] = __ushort_as_bfloat16(f2bf(v - bf2f(h)));
}

// ============================================================================
// K0b: split x. grid 4096 x 256.
// ============================================================================
__global__ void splitx_kernel(const float* __restrict__ x)
{
    int idx4 = blockIdx.x * blockDim.x + threadIdx.x;
    float4 v = ((const float4*)x)[idx4];
    uint16_t h0 = f2bf(v.x), h1 = f2bf(v.y), h2 = f2bf(v.z), h3 = f2bf(v.w);
    *(uint2*)(d_x_hi + (size_t)idx4 * 4) = make_uint2(pack2(h0, h1), pack2(h2, h3));
    *(uint2*)(d_x_lo + (size_t)idx4 * 4) =
        make_uint2(pack2(f2bf(v.x - bf2f(h0)), f2bf(v.y - bf2f(h1))),
                   pack2(f2bf(v.z - bf2f(h2)), f2bf(v.w - bf2f(h3))));
}

// ============================================================================
// K1: HMMA projection GEMM (unchanged). grid (3, 32, 4), 256 thr.
// ============================================================================
#define PJ_WHI   0u
#define PJ_WLO   10240u
#define PJ_XHI   20480u
#define PJ_XLO   29184u
#define PJ_STAGE 37888u
#define PROJ_SMEM 75776

__global__ void __launch_bounds__(256, 2) proj_kernel(const float* __restrict__ b_g,
                                                      const float* __restrict__ b_t,
                                                      const float* __restrict__ b_p)
{
    extern __shared__ char smc[];
    const uint32_t sb = smem_u32(smc);
    const int mt = blockIdx.x;
    const int n0 = blockIdx.y * 128;
    const int b  = blockIdx.z;
    const int tid = threadIdx.x, wid = tid >> 5, lane = tid & 31;
    const int gid = lane >> 2, tig = lane & 3;
    const int obase = mt * 128;

    float acc[16][4];
#pragma unroll
    for (int nf = 0; nf < 16; nf++)
#pragma unroll
        for (int e = 0; e < 4; e++) acc[nf][e] = 0.f;

    auto load_chunk = [&](int st, int kc) {
        uint32_t base = sb + (uint32_t)st * PJ_STAGE;
        for (int idx = tid; idx < 512; idx += 256) {
            int r = idx >> 2, sg = idx & 3;
            cp16(base + PJ_WHI + (uint32_t)r * 80 + sg * 16,
                 d_W_hi + (size_t)(obase + r) * 256 + kc + sg * 8);
            cp16(base + PJ_WLO + (uint32_t)r * 80 + sg * 16,
                 d_W_lo + (size_t)(obase + r) * 256 + kc + sg * 8);
            int xr = idx >> 4, xs = idx & 15;
            cp16(base + PJ_XHI + (uint32_t)xr * 272 + xs * 16,
                 d_x_hi + (size_t)(b * C + kc + xr) * N + n0 + xs * 8);
            cp16(base + PJ_XLO + (uint32_t)xr * 272 + xs * 16,
                 d_x_lo + (size_t)(b * C + kc + xr) * N + n0 + xs * 8);
        }
    };

    load_chunk(0, 0);
    CP_COMMIT();
    for (int c = 0; c < 8; ++c) {
        if (c + 1 < 8) { load_chunk((c + 1) & 1, (c + 1) * 32); CP_COMMIT(); CP_WAIT(1); }
        else           { CP_WAIT(0); }
        __syncthreads();
        uint32_t base = sb + (uint32_t)(c & 1) * PJ_STAGE;
#pragma unroll
        for (int kk = 0; kk < 2; ++kk) {
            uint32_t aaddr = base + PJ_WHI + (uint32_t)(wid * 16 + (lane & 15)) * 80
                           + (uint32_t)(lane >> 4) * 16 + (uint32_t)kk * 32;
            uint32_t ah0, ah1, ah2, ah3, al0, al1, al2, al3;
            ldsm_x4(aaddr, ah0, ah1, ah2, ah3);
            ldsm_x4(aaddr + (PJ_WLO - PJ_WHI), al0, al1, al2, al3);
#pragma unroll
            for (int nf = 0; nf < 16; ++nf) {
                uint32_t baddr = base + PJ_XHI
                               + (uint32_t)(kk * 16 + ((lane >> 3) & 1) * 8 + (lane & 7)) * 272
                               + (uint32_t)(lane >> 4) * (PJ_XLO - PJ_XHI)
                               + (uint32_t)nf * 16;
                uint32_t bh0, bh1, bl0, bl1;
                ldsm_x4_t(baddr, bh0, bh1, bl0, bl1);
                mma_bf16(acc[nf], ah0, ah1, ah2, ah3, bh0, bh1);
                mma_bf16(acc[nf], ah0, ah1, ah2, ah3, bl0, bl1);
                mma_bf16(acc[nf], al0, al1, al2, al3, bh0, bh1);
            }
        }
        __syncthreads();
    }

    const float* bias = (mt == 0) ? b_g : (mt == 1) ? b_t : b_p;
    const int r0 = wid * 16 + gid, r1 = r0 + 8;
    const float br0 = bias[r0], br1 = bias[r1];
#pragma unroll
    for (int nf = 0; nf < 16; ++nf) {
        acc[nf][0] += br0; acc[nf][1] += br0;
        acc[nf][2] += br1; acc[nf][3] += br1;
    }

    if (mt == 0) {
        __nv_bfloat16* dsts[2] = { d_g_hi + (size_t)(b * CI) * N + n0,
                                   d_g_lo + (size_t)(b * CI) * N + n0 };
#pragma unroll
        for (int rnd = 0; rnd < 2; ++rnd) {
#pragma unroll
            for (int nf = 0; nf < 16; ++nf) {
                int ncol = 8 * nf + 2 * tig;
                uint16_t h0 = f2bf(acc[nf][0]), h1 = f2bf(acc[nf][1]);
                uint16_t h2 = f2bf(acc[nf][2]), h3 = f2bf(acc[nf][3]);
                uint32_t v0, v1;
                if (rnd == 0) { v0 = pack2(h0, h1); v1 = pack2(h2, h3); }
                else {
                    v0 = pack2(f2bf(acc[nf][0] - bf2f(h0)), f2bf(acc[nf][1] - bf2f(h1)));
                    v1 = pack2(f2bf(acc[nf][2] - bf2f(h2)), f2bf(acc[nf][3] - bf2f(h3)));
                }
                *(uint32_t*)(smc + (uint32_t)r0 * 272 + (uint32_t)ncol * 2) = v0;
                *(uint32_t*)(smc + (uint32_t)r1 * 272 + (uint32_t)ncol * 2) = v1;
            }
            __syncthreads();
            for (int idx = tid; idx < 2048; idx += 256) {
                int row = idx >> 4, c16 = idx & 15;
                *(uint4*)(dsts[rnd] + (size_t)row * N + c16 * 8) =
                    *(const uint4*)(smc + (uint32_t)row * 272 + (uint32_t)c16 * 16);
            }
            __syncthreads();
        }
    } else {
        __nv_bfloat16* dsts[2];
        dsts[0] = (mt == 1) ? d_thT_hi : d_phT_hi;
        dsts[1] = (mt == 1) ? d_thT_lo : d_phT_lo;
#pragma unroll
        for (int rnd = 0; rnd < 2; ++rnd) {
#pragma unroll
            for (int nf = 0; nf < 16; ++nf) {
                int nc = 8 * nf + 2 * tig;
                uint16_t h0 = f2bf(acc[nf][0]), h1 = f2bf(acc[nf][1]);
                uint16_t h2 = f2bf(acc[nf][2]), h3 = f2bf(acc[nf][3]);
                uint16_t v0, v1, v2, v3;
                if (rnd == 0) { v0 = h0; v1 = h1; v2 = h2; v3 = h3; }
                else {
                    v0 = f2bf(acc[nf][0] - bf2f(h0)); v1 = f2bf(acc[nf][1] - bf2f(h1));
                    v2 = f2bf(acc[nf][2] - bf2f(h2)); v3 = f2bf(acc[nf][3] - bf2f(h3));
                }
                *(__nv_bfloat16*)(smc + (uint32_t)(nc + 0) * 272 + (uint32_t)r0 * 2) = __ushort_as_bfloat16(v0);
                *(__nv_bfloat16*)(smc + (uint32_t)(nc + 1) * 272 + (uint32_t)r0 * 2) = __ushort_as_bfloat16(v1);
                *(__nv_bfloat16*)(smc + (uint32_t)(nc + 0) * 272 + (uint32_t)r1 * 2) = __ushort_as_bfloat16(v2);
                *(__nv_bfloat16*)(smc + (uint32_t)(nc + 1) * 272 + (uint32_t)r1 * 2) = __ushort_as_bfloat16(v3);
            }
            __syncthreads();
            for (int idx = tid; idx < 2048; idx += 256) {
                int row = idx >> 4, c16 = idx & 15;
                *(uint4*)(dsts[rnd] + (size_t)(b * N + n0 + row) * CI + c16 * 8) =
                    *(const uint4*)(smc + (uint32_t)row * 272 + (uint32_t)c16 * 16);
            }
            __syncthreads();
        }
    }
}

// ============================================================================
// K2: HMMA flash attention, 512 threads / 16 warps (4 per SMSP).
// Warp (rg, h): rg in [0,8) owns 16 query rows; h in {0,1}.
//   QK : S[16 rows][m-half 32] (s = 4 frags), exp, P -> smem (bf16 hi/lo)
//   PV : Y[16 rows][c-half 64] over FULL m (P from smem) -> complete partials
// l rowsums pair-summed at the end. Tiles XOR-swizzled (chunk ^= row&7).
// grid (32, 4), dyn smem 230400 B.
// SMEM: TH hi/lo 2x32768 | 2 stages x (PHI hi/lo 2x16384 + G hi/lo 2x16384)
//       | P hi/lo 2x16384 | lred 1024
// ============================================================================
#define A_TH_HI    0u
#define A_TH_LO    32768u
#define A_OFF_ST   65536u
#define A_PHI_HI   0u
#define A_PHI_LO   16384u
#define A_G_HI     32768u
#define A_G_LO     49152u
#define A_STAGE    65536u
#define A_P_HI     196608u
#define A_P_LO     212992u
#define A_LRED     229376u
#define ATTN_SMEM  230400

__global__ void __launch_bounds__(512, 1) attn_kernel()
{
    extern __shared__ char smc[];
    const uint32_t sb = smem_u32(smc);
    const int b   = blockIdx.y;
    const int n0  = blockIdx.x * 128;
    const int tid = threadIdx.x;
    const int wid = tid >> 5, lane = tid & 31;
    const int gid = lane >> 2, tig = lane & 3;
    const int sel = lane >> 3, lr = lane & 7;
    const int rg = wid >> 1, h = wid & 1;

    // ---- theta tile -> smem once (swizzled: 128 rows x 256B, 16 chunks) ----
    {
        const __nv_bfloat16* th = d_thT_hi + (size_t)(b * N + n0) * CI;
        const __nv_bfloat16* tl = d_thT_lo + (size_t)(b * N + n0) * CI;
        for (int idx = tid; idx < 128 * 16; idx += 512) {
            int r = idx >> 4, c = idx & 15;
            uint32_t o = (uint32_t)r * 256 + (uint32_t)((c ^ (r & 7)) * 16);
            cp16(sb + A_TH_HI + o, th + (size_t)r * CI + c * 8);
            cp16(sb + A_TH_LO + o, tl + (size_t)r * CI + c * 8);
        }
    }
    CP_COMMIT();

    auto stage_load = [&](int st, int it) {
        const int m0 = it * 64;
        uint32_t base = sb + A_OFF_ST + (uint32_t)st * A_STAGE;
        const __nv_bfloat16* ph = d_phT_hi + (size_t)(b * N + m0) * CI;
        const __nv_bfloat16* pl = d_phT_lo + (size_t)(b * N + m0) * CI;
        for (int idx = tid; idx < 64 * 16; idx += 512) {
            int r = idx >> 4, c = idx & 15;
            uint32_t o = (uint32_t)r * 256 + (uint32_t)((c ^ (r & 7)) * 16);
            cp16(base + A_PHI_HI + o, ph + (size_t)r * CI + c * 8);
            cp16(base + A_PHI_LO + o, pl + (size_t)r * CI + c * 8);
        }
        const __nv_bfloat16* gh = d_g_hi + (size_t)b * CI * N + m0;
        const __nv_bfloat16* gl = d_g_lo + (size_t)b * CI * N + m0;
        for (int idx = tid; idx < 128 * 8; idx += 512) {
            int r = idx >> 3, c = idx & 7;
            uint32_t o = (uint32_t)r * 128 + (uint32_t)((c ^ (r & 7)) * 16);
            cp16(base + A_G_HI + o, gh + (size_t)r * N + c * 8);
            cp16(base + A_G_LO + o, gl + (size_t)r * N + c * 8);
        }
    };

    stage_load(0, 0);
    CP_COMMIT();

    float y[8][4];
#pragma unroll
    for (int t = 0; t < 8; t++)
#pragma unroll
        for (int e = 0; e < 4; e++) y[t][e] = 0.f;
    float l_lo = 0.f, l_hi = 0.f;

    // A-frag (theta & P) fixed per-thread row
    const uint32_t arow = (uint32_t)(16 * rg + (lane & 15));
    const int prow0 = 16 * rg + gid, prow1 = prow0 + 8;

    for (int it = 0; it < 64; ++it) {
        if (it + 1 < 64) { stage_load((it + 1) & 1, it + 1); CP_COMMIT(); CP_WAIT(1); }
        else             { CP_WAIT(0); }
        __syncthreads();  // B1: stage ready (all threads' cp.async), Psm free
        const uint32_t stb = sb + A_OFF_ST + (uint32_t)(it & 1) * A_STAGE;

        // ---- QK: S[16 x 32] for this warp's m-half ----
        float s[4][4];
#pragma unroll
        for (int j = 0; j < 4; j++)
#pragma unroll
            for (int e = 0; e < 4; e++) s[j][e] = 0.f;

#pragma unroll
        for (int k = 0; k < 8; k++) {
            uint32_t ach = (uint32_t)((2 * k + (lane >> 4)) ^ (arow & 7));
            uint32_t aoff = arow * 256 + ach * 16;
            uint32_t ah0, ah1, ah2, ah3, al0, al1, al2, al3;
            ldsm_x4(sb + A_TH_HI + aoff, ah0, ah1, ah2, ah3);
            ldsm_x4(sb + A_TH_LO + aoff, al0, al1, al2, al3);
#pragma unroll
            for (int j = 0; j < 4; j++) {
                uint32_t brow = (uint32_t)(32 * h + 8 * j + lr);
                uint32_t bch  = (uint32_t)((2 * k + (sel & 1)) ^ lr);
                uint32_t baddr = stb + ((sel >= 2) ? A_PHI_LO : A_PHI_HI)
                               + brow * 256 + bch * 16;
                uint32_t bh0, bh1, bl0, bl1;
                ldsm_x4(baddr, bh0, bh1, bl0, bl1);
                mma_bf16(s[j], ah0, ah1, ah2, ah3, bh0, bh1);
                mma_bf16(s[j], ah0, ah1, ah2, ah3, bl0, bl1);
                mma_bf16(s[j], al0, al1, al2, al3, bh0, bh1);
            }
        }

        // ---- exp + rowsum + P hi/lo -> smem ----
        float rs0 = 0.f, rs1 = 0.f;
#pragma unroll
        for (int j = 0; j < 4; j++) {
#pragma unroll
            for (int e = 0; e < 4; e++) s[j][e] = __expf(s[j][e]);
            rs0 += s[j][0] + s[j][1];
            rs1 += s[j][2] + s[j][3];
        }
#pragma unroll
        for (int j = 0; j < 4; j++) {
            uint16_t h00 = f2bf(s[j][0]), h01 = f2bf(s[j][1]);
            uint16_t h02 = f2bf(s[j][2]), h03 = f2bf(s[j][3]);
            uint32_t hi0 = pack2(h00, h01), hi1 = pack2(h02, h03);
            uint32_t lo0 = pack2(f2bf(s[j][0] - bf2f(h00)), f2bf(s[j][1] - bf2f(h01)));
            uint32_t lo1 = pack2(f2bf(s[j][2] - bf2f(h02)), f2bf(s[j][3] - bf2f(h03)));
            uint32_t c = (uint32_t)(4 * h + j);
            uint32_t o0 = (uint32_t)prow0 * 128 + ((c ^ (uint32_t)(prow0 & 7)) * 16) + 4 * tig;
            uint32_t o1 = (uint32_t)prow1 * 128 + ((c ^ (uint32_t)(prow1 & 7)) * 16) + 4 * tig;
            sts32(sb + A_P_HI + o0, hi0);
            sts32(sb + A_P_LO + o0, lo0);
            sts32(sb + A_P_HI + o1, hi1);
            sts32(sb + A_P_LO + o1, lo1);
        }
        rs0 += __shfl_xor_sync(0xffffffffu, rs0, 1);
        rs0 += __shfl_xor_sync(0xffffffffu, rs0, 2);
        rs1 += __shfl_xor_sync(0xffffffffu, rs1, 1);
        rs1 += __shfl_xor_sync(0xffffffffu, rs1, 2);
        l_lo += rs0;
        l_hi += rs1;

        __syncthreads();  // B2: P visible to partner warps

        // ---- PV: Y[16 x 64] over full m (k-outer: P frags reused for 8 ct) ----
#pragma unroll
        for (int k = 0; k < 4; k++) {
            uint32_t ach = (uint32_t)((2 * k + (lane >> 4)) ^ (arow & 7));
            uint32_t aoff = arow * 128 + ach * 16;
            uint32_t ph0, ph1, ph2, ph3, pl0, pl1, pl2, pl3;
            ldsm_x4(sb + A_P_HI + aoff, ph0, ph1, ph2, ph3);
            ldsm_x4(sb + A_P_LO + aoff, pl0, pl1, pl2, pl3);
#pragma unroll
            for (int ct = 0; ct < 8; ct++) {
                uint32_t grow = (uint32_t)(64 * h + 8 * ct + lr);
                uint32_t gch  = (uint32_t)((2 * k + (sel & 1)) ^ lr);
                uint32_t gaddr = stb + ((sel >= 2) ? A_G_LO : A_G_HI)
                               + grow * 128 + gch * 16;
                uint32_t gh0, gh1, gl0, gl1;
                ldsm_x4(gaddr, gh0, gh1, gl0, gl1);
                mma_bf16(y[ct], ph0, ph1, ph2, ph3, gh0, gh1);
                mma_bf16(y[ct], ph0, ph1, ph2, ph3, gl0, gl1);
                mma_bf16(y[ct], pl0, pl1, pl2, pl3, gh0, gh1);
            }
        }
        __syncthreads();  // B3: protect stage + Psm for next iter
    }

    // ---- pair-sum rowsums l, normalize, transpose, write ----
    float* lsm = (float*)(smc + A_LRED);  // [2][128]
    if (tig == 0) {
        lsm[h * 128 + prow0] = l_lo;
        lsm[h * 128 + prow1] = l_hi;
    }
    __syncthreads();
    const float inv0 = 1.f / (lsm[prow0] + lsm[128 + prow0]);
    const float inv1 = 1.f / (lsm[prow1] + lsm[128 + prow1]);

    float* ysm = (float*)smc;  // [128 c][pitch 132] floats (overwrites theta/stages)
    __syncthreads();           // everyone past lsm reads before overwrite
#pragma unroll
    for (int ct = 0; ct < 8; ct++) {
        int c = 64 * h + 8 * ct + 2 * tig;
        ysm[(c + 0) * 132 + prow0] = y[ct][0] * inv0;
        ysm[(c + 1) * 132 + prow0] = y[ct][1] * inv0;
        ysm[(c + 0) * 132 + prow1] = y[ct][2] * inv1;
        ysm[(c + 1) * 132 + prow1] = y[ct][3] * inv1;
    }
    __syncthreads();
    for (int idx = tid; idx < 128 * 128; idx += 512) {
        int c = idx >> 7, n = idx & 127;
        d_y[(size_t)(b * CI + c) * N + n0 + n] = ysm[c * 132 + n];
    }
}

// ============================================================================
// K3: W_y = w_out @ y + b_out + deterministic BN partials. grid (4,32,4), 256.
// ============================================================================
__global__ void wy_kernel(const float* __restrict__ w_out, const float* __restrict__ b_out)
{
    __shared__ float Ws[32][65];
    __shared__ float Ys[32][128];
    const int b  = blockIdx.z;
    const int n0 = blockIdx.y * 128;
    const int o0 = blockIdx.x * 64;
    const int tid = threadIdx.x;
    const int tx = tid & 15, ty = tid >> 4;

    float acc[4][8];
#pragma unroll
    for (int i = 0; i < 4; i++)
#pragma unroll
        for (int j = 0; j < 8; j++) acc[i][j] = 0.f;

    for (int kc = 0; kc < CI; kc += 32) {
        for (int idx = tid; idx < 64 * 32; idx += 256) {
            int o = idx >> 5, k = idx & 31;
            Ws[k][o] = w_out[(o0 + o) * CI + kc + k];
        }
        for (int idx = tid; idx < 32 * 128; idx += 256) {
            int k = idx >> 7, n = idx & 127;
            Ys[k][n] = d_y[(size_t)(b * CI + kc + k) * N + n0 + n];
        }
        __syncthreads();
#pragma unroll 4
        for (int k = 0; k < 32; k++) {
            float a0 = Ws[k][ty * 4 + 0], a1 = Ws[k][ty * 4 + 1];
            float a2 = Ws[k][ty * 4 + 2], a3 = Ws[k][ty * 4 + 3];
            const float4 v0 = *(const float4*)&Ys[k][tx * 8];
            const float4 v1 = *(const float4*)&Ys[k][tx * 8 + 4];
            float bv[8] = {v0.x, v0.y, v0.z, v0.w, v1.x, v1.y, v1.z, v1.w};
#pragma unroll
            for (int j = 0; j < 8; j++) {
                acc[0][j] += a0 * bv[j];
                acc[1][j] += a1 * bv[j];
                acc[2][j] += a2 * bv[j];
                acc[3][j] += a3 * bv[j];
            }
        }
        __syncthreads();
    }

#pragma unroll
    for (int i = 0; i < 4; i++) {
        int oc = o0 + ty * 4 + i;
        float bb = b_out[oc];
        float s = 0.f, q = 0.f;
        float* p = d_wy + (size_t)(b * C + oc) * N + n0 + tx * 8;
#pragma unroll
        for (int j = 0; j < 8; j++) {
            float vv = acc[i][j] + bb;
            p[j] = vv;
            s += vv;
            q += vv * vv;
        }
#pragma unroll
        for (int off = 1; off < 16; off <<= 1) {
            s += __shfl_xor_sync(0xffffffffu, s, off);
            q += __shfl_xor_sync(0xffffffffu, q, off);
        }
        if (tx == 0) {
            int part = b * 32 + blockIdx.y;
            d_psum[oc * 128 + part] = s;
            d_psq[oc * 128 + part]  = q;
        }
    }
}

// ============================================================================
// K4: reduce BN partials. grid 256, 32 threads.
// ============================================================================
__global__ void bnstat_kernel(const float* __restrict__ gamma, const float* __restrict__ beta)
{
    int c = blockIdx.x, t = threadIdx.x;
    float s = 0.f, q = 0.f;
#pragma unroll
    for (int p = t; p < 128; p += 32) {
        s += d_psum[c * 128 + p];
        q += d_psq[c * 128 + p];
    }
#pragma unroll
    for (int off = 1; off < 32; off <<= 1) {
        s += __shfl_xor_sync(0xffffffffu, s, off);
        q += __shfl_xor_sync(0xffffffffu, q, off);
    }
    if (t == 0) {
        const float invn = 1.f / 16384.f;
        float mean = s * invn;
        float var  = q * invn - mean * mean;
        float sc   = gamma[c] * rsqrtf(var + 1e-5f);
        d_bnA[c] = sc;
        d_bnB[c] = beta[c] - mean * sc;
    }
}

// ============================================================================
// K5: out = W_y * scale[c] + shift[c] + x
// ============================================================================
__global__ void bnadd_kernel(const float* __restrict__ x, float* __restrict__ out)
{
    int idx4 = blockIdx.x * blockDim.x + threadIdx.x;
    if (idx4 >= B * C * N / 4) return;
    int c = (idx4 >> 10) & (C - 1);
    float sc = d_bnA[c], bb = d_bnB[c];
    float4 w  = ((const float4*)d_wy)[idx4];
    float4 xv = ((const float4*)x)[idx4];
    float4 r;
    r.x = w.x * sc + bb + xv.x;
    r.y = w.y * sc + bb + xv.y;
    r.z = w.z * sc + bb + xv.z;
    r.w = w.w * sc + bb + xv.w;
    ((float4*)out)[idx4] = r;
}

// ============================================================================
extern "C" void kernel_launch(void* const* d_in, const int* in_sizes, int n_in,
                              void* d_out, int out_size)
{
    const float* x     = (const float*)d_in[0];
    const float* w_g   = (const float*)d_in[1];
    const float* b_g   = (const float*)d_in[2];
    const float* w_t   = (const float*)d_in[3];
    const float* b_t   = (const float*)d_in[4];
    const float* w_p   = (const float*)d_in[5];
    const float* b_p   = (const float*)d_in[6];
    const float* w_o   = (const float*)d_in[7];
    const float* b_o   = (const float*)d_in[8];
    const float* gamma = (const float*)d_in[9];
    const float* beta  = (const float*)d_in[10];
    float* out = (float*)d_out;

    cudaFuncSetAttribute(proj_kernel, cudaFuncAttributeMaxDynamicSharedMemorySize, PROJ_SMEM);
    cudaFuncSetAttribute(attn_kernel, cudaFuncAttributeMaxDynamicSharedMemorySize, ATTN_SMEM);

    splitw_kernel<<<384, 256>>>(w_g, w_t, w_p);
    splitx_kernel<<<4096, 256>>>(x);
    proj_kernel<<<dim3(3, 32, 4), 256, PROJ_SMEM>>>(b_g, b_t, b_p);
    attn_kernel<<<dim3(32, 4), 512, ATTN_SMEM>>>();
    wy_kernel<<<dim3(4, 32, 4), 256>>>(w_o, b_o);
    bnstat_kernel<<<256, 32>>>(gamma, beta);
    bnadd_kernel<<<4096, 256>>>(x, out);
}